// round 1
// baseline (speedup 1.0000x reference)
#include <cuda_runtime.h>
#include <math.h>

#define Bb     64
#define NN     8192
#define WW     64
#define MODES  16
#define NL     4
#define JD     32          // 2*MODES real coefficients
#define KF     96          // 64 channels + 32 basis rows

// ---------------- device scratch (static, allocation-free) ----------------
__device__ float g_h0[(size_t)Bb * WW * NN];          // 128 MB
__device__ float g_h1[(size_t)Bb * WW * NN];          // 128 MB
__device__ float g_part[4][Bb * WW * JD];             // k-split DFT partials
__device__ float g_mixed[Bb * WW * JD];               // scaled mixed modes
__device__ float g_basis_f[NN * JD];                  // [n][j] forward basis
__device__ float g_basis_i[JD * NN];                  // [j][n] inverse basis
__device__ float g_wt[NL * MODES * WW * 2 * WW];      // [(l,m,i)][re(64)|im(64)]

// ---------------- basis tables: cos(2pi m n/N), -sin(2pi m n/N) -----------
__global__ void init_basis_kernel() {
    int idx = blockIdx.x * blockDim.x + threadIdx.x;   // NN*MODES = 131072
    if (idx >= NN * MODES) return;
    int m = idx & (MODES - 1);
    int n = idx >> 4;
    int prod = (n * m) & (NN - 1);                     // exact mod-N reduction
    float ang = (float)prod * (6.2831853071795864769f / (float)NN);
    float s, c;
    sincosf(ang, &s, &c);
    g_basis_f[n * JD + 2 * m]     = c;
    g_basis_f[n * JD + 2 * m + 1] = -s;
    g_basis_i[(2 * m) * NN + n]     = c;
    g_basis_i[(2 * m + 1) * NN + n] = -s;
}

// ---------------- transpose spectral weights to [(l,m,i)][o] --------------
__global__ void transpose_w_kernel(const float* __restrict__ swr,
                                   const float* __restrict__ swi) {
    int idx = blockIdx.x * blockDim.x + threadIdx.x;   // NL*MODES*W*W = 262144
    if (idx >= NL * MODES * WW * WW) return;
    int o = idx & 63;
    int i = (idx >> 6) & 63;
    int m = (idx >> 12) & 15;
    int l = idx >> 16;
    int src = (((l * WW + i) * WW + o) << 4) + m;      // sw[l][i][o][m]
    int dst = (((l * MODES + m) * WW + i) << 7);       // g_wt[(l,m,i)][...]
    g_wt[dst + o]      = swr[src];
    g_wt[dst + 64 + o] = swi[src];
}

// ---------------- fc0: [B,N,2] -> h0[B,W,N] -------------------------------
__global__ void fc0_kernel(const float* __restrict__ x, const float* __restrict__ t,
                           const float* __restrict__ w, const float* __restrict__ bias) {
    int g = blockIdx.x * blockDim.x + threadIdx.x;     // B*N
    float xv = x[g], tv = t[g];
    int b = g >> 13, n = g & (NN - 1);
    float* hp = g_h0 + (size_t)b * WW * NN + n;
#pragma unroll 8
    for (int c = 0; c < WW; c++)
        hp[(size_t)c * NN] = fmaf(xv, __ldg(w + c), fmaf(tv, __ldg(w + WW + c), __ldg(bias + c)));
}

// ---------------- forward DFT GEMM: [4096 x 8192] @ [8192 x 32] -----------
// grid (64 row-blocks, 4 k-splits), 256 threads. Deterministic partial sums.
__global__ void __launch_bounds__(256) dft_kernel(int src) {
    const float* __restrict__ h = src ? g_h1 : g_h0;
    __shared__ float sh[64][64];
    __shared__ float sb[64][32];
    int row0 = blockIdx.x * 64;
    int k0b  = blockIdx.y * 2048;
    int tid = threadIdx.x, tx = tid & 31, ty = tid >> 5;
    float acc[8];
#pragma unroll
    for (int u = 0; u < 8; u++) acc[u] = 0.0f;

    for (int kt = 0; kt < 32; kt++) {
        int k0 = k0b + kt * 64;
        __syncthreads();
        for (int idx = tid; idx < 64 * 64; idx += 256) {
            int r = idx >> 6, k = idx & 63;
            sh[r][k] = h[(size_t)(row0 + r) * NN + k0 + k];
        }
        for (int idx = tid; idx < 64 * 32; idx += 256) {
            int n = idx >> 5, j = idx & 31;
            sb[n][j] = g_basis_f[(k0 + n) * JD + j];
        }
        __syncthreads();
#pragma unroll
        for (int k4 = 0; k4 < 16; k4++) {
            float b0 = sb[4 * k4 + 0][tx];
            float b1 = sb[4 * k4 + 1][tx];
            float b2 = sb[4 * k4 + 2][tx];
            float b3 = sb[4 * k4 + 3][tx];
#pragma unroll
            for (int u = 0; u < 8; u++) {
                float4 hv = *(const float4*)&sh[ty * 8 + u][k4 * 4];
                acc[u] = fmaf(hv.x, b0, fmaf(hv.y, b1, fmaf(hv.z, b2, fmaf(hv.w, b3, acc[u]))));
            }
        }
    }
#pragma unroll
    for (int u = 0; u < 8; u++)
        g_part[blockIdx.y][(row0 + ty * 8 + u) * JD + tx] = acc[u];
}

// ---------------- mode mixing + irfft scaling -----------------------------
// grid 1024 = (b,m), 64 threads (o). out: g_mixed[(b,o)][2m]=Re*s, [2m+1]=Im*s
__global__ void mode_mix_kernel(int l) {
    int b = blockIdx.x >> 4;
    int m = blockIdx.x & 15;
    int o = threadIdx.x;
    __shared__ float Fr[64], Fi[64];
    int base = (b * WW + o) * JD + 2 * m;
    Fr[o] = g_part[0][base] + g_part[1][base] + g_part[2][base] + g_part[3][base];
    Fi[o] = g_part[0][base + 1] + g_part[1][base + 1] + g_part[2][base + 1] + g_part[3][base + 1];
    __syncthreads();
    float ar = 0.0f, ai = 0.0f;
    const float* __restrict__ wp = g_wt + (size_t)((l * MODES + m) * WW) * 128;
#pragma unroll 4
    for (int i = 0; i < WW; i++) {
        float fr = Fr[i], fi = Fi[i];
        float wr = wp[i * 128 + o];
        float wi = wp[i * 128 + 64 + o];
        ar = fmaf(fr, wr, fmaf(-fi, wi, ar));
        ai = fmaf(fr, wi, fmaf(fi, wr, ai));
    }
    float scale = (m == 0) ? (1.0f / NN) : (2.0f / NN);
    g_mixed[base]     = ar * scale;
    g_mixed[base + 1] = ai * scale;
}

__device__ __forceinline__ float gelu_exact(float v) {
    return 0.5f * v * (1.0f + erff(v * 0.70710678118654752f));
}

// ---------------- fused layer: irfft + pointwise conv + bias + GELU -------
// per block (b, n-tile of 128): C[64 x 128] = A[64 x 96] @ B[96 x 128]
__global__ void __launch_bounds__(256) fused_layer_kernel(int src,
        const float* __restrict__ cw, const float* __restrict__ cb,
        int l, int apply_gelu) {
    extern __shared__ float smem[];
    float* As = smem;                 // 64*96
    float* Bs = smem + 64 * KF;       // 96*128
    const float* __restrict__ hin = src ? g_h1 : g_h0;
    float* __restrict__ hout      = src ? g_h0 : g_h1;
    int b  = blockIdx.y;
    int n0 = blockIdx.x * 128;
    int tid = threadIdx.x, tx = tid & 31, ty = tid >> 5;

    for (int idx = tid; idx < 64 * 64; idx += 256) {
        int o = idx >> 6, c = idx & 63;
        As[o * KF + c] = cw[(l * WW + o) * WW + c];
    }
    for (int idx = tid; idx < 64 * 32; idx += 256) {
        int o = idx >> 5, j = idx & 31;
        As[o * KF + 64 + j] = g_mixed[(b * WW + o) * JD + j];
    }
    for (int idx = tid; idx < 64 * 128; idx += 256) {
        int c = idx >> 7, n = idx & 127;
        Bs[c * 128 + n] = hin[(size_t)(b * WW + c) * NN + n0 + n];
    }
    for (int idx = tid; idx < 32 * 128; idx += 256) {
        int j = idx >> 7, n = idx & 127;
        Bs[(64 + j) * 128 + n] = g_basis_i[j * NN + n0 + n];
    }
    __syncthreads();

    float acc[8][4];
#pragma unroll
    for (int u = 0; u < 8; u++)
#pragma unroll
        for (int v = 0; v < 4; v++) acc[u][v] = 0.0f;

#pragma unroll
    for (int k4 = 0; k4 < KF / 4; k4++) {
        float4 a4[8];
#pragma unroll
        for (int u = 0; u < 8; u++)
            a4[u] = *(const float4*)&As[(ty + 8 * u) * KF + 4 * k4];
#pragma unroll
        for (int kk = 0; kk < 4; kk++) {
            float bv[4];
#pragma unroll
            for (int v = 0; v < 4; v++) bv[v] = Bs[(4 * k4 + kk) * 128 + tx + 32 * v];
#pragma unroll
            for (int u = 0; u < 8; u++) {
                float a = (&a4[u].x)[kk];
#pragma unroll
                for (int v = 0; v < 4; v++) acc[u][v] = fmaf(a, bv[v], acc[u][v]);
            }
        }
    }

#pragma unroll
    for (int u = 0; u < 8; u++) {
        int o = ty + 8 * u;
        float bias = __ldg(cb + l * WW + o);
        float* op = hout + (size_t)(b * WW + o) * NN + n0;
#pragma unroll
        for (int v = 0; v < 4; v++) {
            float val = acc[u][v] + bias;
            if (apply_gelu) val = gelu_exact(val);
            op[tx + 32 * v] = val;
        }
    }
}

// ---------------- head: fc1 + GELU + fc2 ----------------------------------
// per block (b, n-tile 128): G[128j x 128n] = gelu(W1^T @ H + b1); out = w2.G
__global__ void __launch_bounds__(256) head_kernel(int src,
        const float* __restrict__ fc1w, const float* __restrict__ fc1b,
        const float* __restrict__ fc2w, const float* __restrict__ fc2b,
        float* __restrict__ out) {
    extern __shared__ float smem[];
    float* Hs  = smem;                 // 64*128
    float* W1s = smem + 64 * 128;      // 64*128 (j-permuted)
    float* Gs  = W1s + 64 * 128;       // 128*128
    __shared__ float ps[256];
    const float* __restrict__ h = src ? g_h1 : g_h0;
    int b = blockIdx.y, n0 = blockIdx.x * 128;
    int tid = threadIdx.x, tx = tid & 31, ty = tid >> 5;

    for (int idx = tid; idx < 64 * 128; idx += 256) {
        int c = idx >> 7, n = idx & 127;
        Hs[c * 128 + n] = h[(size_t)(b * WW + c) * NN + n0 + n];
    }
    // permute j so each thread's 16 j's are contiguous: perm(j)=(j&7)*16+(j>>3)
    for (int idx = tid; idx < 64 * 128; idx += 256) {
        int k = idx >> 7, j = idx & 127;
        W1s[k * 128 + ((j & 7) * 16 + (j >> 3))] = fc1w[idx];
    }
    __syncthreads();

    float acc[16][4];
#pragma unroll
    for (int u = 0; u < 16; u++)
#pragma unroll
        for (int v = 0; v < 4; v++) acc[u][v] = 0.0f;

#pragma unroll 4
    for (int k = 0; k < 64; k++) {
        float bv[4];
#pragma unroll
        for (int v = 0; v < 4; v++) bv[v] = Hs[k * 128 + tx + 32 * v];
        float4 a4[4];
#pragma unroll
        for (int q = 0; q < 4; q++)
            a4[q] = *(const float4*)&W1s[k * 128 + ty * 16 + 4 * q];
#pragma unroll
        for (int u = 0; u < 16; u++) {
            float a = (&a4[u >> 2].x)[u & 3];
#pragma unroll
            for (int v = 0; v < 4; v++) acc[u][v] = fmaf(a, bv[v], acc[u][v]);
        }
    }

#pragma unroll
    for (int u = 0; u < 16; u++) {
        int j = ty + 8 * u;                 // inverse of perm: slot u at thread ty
        float bj = __ldg(fc1b + j);
#pragma unroll
        for (int v = 0; v < 4; v++) {
            float val = gelu_exact(acc[u][v] + bj);
            Gs[j * 128 + tx + 32 * v] = val;
        }
    }
    __syncthreads();

    int n = tid & 127, half = tid >> 7;
    float s = 0.0f;
    int j0 = half * 64;
#pragma unroll 8
    for (int j = 0; j < 64; j++)
        s = fmaf(__ldg(fc2w + j0 + j), Gs[(j0 + j) * 128 + n], s);
    ps[tid] = s;
    __syncthreads();
    if (tid < 128)
        out[(size_t)b * NN + n0 + tid] = ps[tid] + ps[128 + tid] + __ldg(fc2b);
}

// Careful with perm inverse: thread (ty) slot u holds W1s offset ty*16+u,
// and perm(j) = (j&7)*16 + (j>>3) = ty*16+u  =>  j&7 = ty, j>>3 = u  => j = u*8+ty.
// The epilogue above must use j = u*8+ty? Check: perm maps j -> (j&7)*16+(j>>3).
// We READ positions ty*16 + u. Setting (j&7)=ty and (j>>3)=u gives j = 8*u + ty.
// So epilogue j = ty + 8*u is CORRECT (matches 8*u+ty).

// ---------------- launch orchestration ------------------------------------
extern "C" void kernel_launch(void* const* d_in, const int* in_sizes, int n_in,
                              void* d_out, int out_size) {
    const float* x     = (const float*)d_in[0];
    const float* t     = (const float*)d_in[1];
    const float* fc0_w = (const float*)d_in[2];
    const float* fc0_b = (const float*)d_in[3];
    const float* sw_r  = (const float*)d_in[4];
    const float* sw_i  = (const float*)d_in[5];
    const float* cw    = (const float*)d_in[6];
    const float* cb    = (const float*)d_in[7];
    const float* fc1_w = (const float*)d_in[8];
    const float* fc1_b = (const float*)d_in[9];
    const float* fc2_w = (const float*)d_in[10];
    const float* fc2_b = (const float*)d_in[11];
    float* out = (float*)d_out;

    cudaFuncSetAttribute(fused_layer_kernel,
                         cudaFuncAttributeMaxDynamicSharedMemorySize, (64 * KF + KF * 128) * 4);
    cudaFuncSetAttribute(head_kernel,
                         cudaFuncAttributeMaxDynamicSharedMemorySize, (64 * 128 + 64 * 128 + 128 * 128) * 4);

    init_basis_kernel<<<512, 256>>>();
    transpose_w_kernel<<<1024, 256>>>(sw_r, sw_i);
    fc0_kernel<<<2048, 256>>>(x, t, fc0_w, fc0_b);

    int src = 0;  // current h buffer: 0 -> g_h0
    for (int l = 0; l < NL; l++) {
        dft_kernel<<<dim3(64, 4), 256>>>(src);
        mode_mix_kernel<<<1024, 64>>>(l);
        fused_layer_kernel<<<dim3(64, 64), 256, (64 * KF + KF * 128) * 4>>>(
            src, cw, cb, l, (l < NL - 1) ? 1 : 0);
        src ^= 1;
    }
    head_kernel<<<dim3(64, 64), 256, (64 * 128 + 64 * 128 + 128 * 128) * 4>>>(
        src, fc1_w, fc1_b, fc2_w, fc2_b, out);
}

// round 8
// speedup vs baseline: 1.0782x; 1.0782x over previous
#include <cuda_runtime.h>
#include <math.h>

#define Bb     64
#define NN     8192
#define WW     64
#define MODES  16
#define NL     4
#define JD     32          // 2*MODES real coefficients
#define KF     96          // 64 channels + 32 basis rows
#define NT     64          // n-tiles of 128
#define TN     128

typedef unsigned long long ull;

// ---------------- device scratch (static, allocation-free) ----------------
__device__ float g_h0[(size_t)Bb * WW * NN];          // 128 MB
__device__ float g_h1[(size_t)Bb * WW * NN];          // 128 MB
__device__ float g_part[(size_t)Bb * NT * WW * JD];   // per-tile DFT partials (32 MB)
__device__ float g_mixed[Bb * WW * JD];               // scaled mixed modes
__device__ float g_basis[NN * JD];                    // [n][j]: cos / -sin
__device__ float g_wt[NL * MODES * WW * 2 * WW];      // [(l,m,i)][re(64)|im(64)]

// ---------------- packed f32x2 helpers ------------------------------------
__device__ __forceinline__ ull pk2(float lo, float hi) {
    ull r; asm("mov.b64 %0,{%1,%2};" : "=l"(r) : "f"(lo), "f"(hi)); return r;
}
__device__ __forceinline__ void upk2(ull v, float& lo, float& hi) {
    asm("mov.b64 {%0,%1},%2;" : "=f"(lo), "=f"(hi) : "l"(v));
}
__device__ __forceinline__ ull fma2(ull a, ull b, ull c) {
    ull d; asm("fma.rn.f32x2 %0,%1,%2,%3;" : "=l"(d) : "l"(a), "l"(b), "l"(c)); return d;
}

__device__ __forceinline__ float gelu_exact(float v) {
    return 0.5f * v * (1.0f + erff(v * 0.70710678118654752f));
}

// ---------------- basis table: [n][2m]=cos, [2m+1]=-sin --------------------
__global__ void init_basis_kernel() {
    int idx = blockIdx.x * blockDim.x + threadIdx.x;   // NN*MODES
    if (idx >= NN * MODES) return;
    int m = idx & (MODES - 1);
    int n = idx >> 4;
    int prod = (n * m) & (NN - 1);
    float ang = (float)prod * (6.2831853071795864769f / (float)NN);
    float s, c;
    sincosf(ang, &s, &c);
    g_basis[n * JD + 2 * m]     = c;
    g_basis[n * JD + 2 * m + 1] = -s;
}

// ---------------- transpose spectral weights to [(l,m,i)][re|im] -----------
__global__ void transpose_w_kernel(const float* __restrict__ swr,
                                   const float* __restrict__ swi) {
    int idx = blockIdx.x * blockDim.x + threadIdx.x;   // NL*MODES*W*W
    if (idx >= NL * MODES * WW * WW) return;
    int o = idx & 63;
    int i = (idx >> 6) & 63;
    int m = (idx >> 12) & 15;
    int l = idx >> 16;
    int src = (((l * WW + i) * WW + o) << 4) + m;
    int dst = (((l * MODES + m) * WW + i) << 7);
    g_wt[dst + o]      = swr[src];
    g_wt[dst + 64 + o] = swi[src];
}

// ---------------- shared DFT-partial phase ---------------------------------
// Ts: [64][132] post-activation tile; Ej: [32][130] basis (j-major).
// Writes P[o][j] = sum_n Ts[o][n]*Ej[j][n] to g_part[(b,nt)][o][j].
__device__ __forceinline__ void dft_phase(const float* __restrict__ Ts,
                                          const float* __restrict__ Ej,
                                          int b, int nt, int tx, int ty) {
    ull acc[8];
#pragma unroll
    for (int u = 0; u < 8; u++) acc[u] = 0ULL;
#pragma unroll 8
    for (int n2 = 0; n2 < 64; n2++) {
        ull e2 = *(const ull*)&Ej[tx * 130 + 2 * n2];
#pragma unroll
        for (int u = 0; u < 8; u++) {
            ull t2 = *(const ull*)&Ts[(ty + 8 * u) * 132 + 2 * n2];
            acc[u] = fma2(t2, e2, acc[u]);
        }
    }
    float* gp = g_part + (size_t)(b * NT + nt) * WW * JD;
#pragma unroll
    for (int u = 0; u < 8; u++) {
        float lo, hi; upk2(acc[u], lo, hi);
        gp[(ty + 8 * u) * JD + tx] = lo + hi;
    }
}

// ---------------- fc0 tile + DFT partial -----------------------------------
__global__ void __launch_bounds__(256) fc0_dft_kernel(
        const float* __restrict__ x, const float* __restrict__ t,
        const float* __restrict__ w, const float* __restrict__ bias) {
    extern __shared__ float sm[];
    float* Ts = sm;                // 64*132
    float* Ej = sm + 64 * 132;     // 32*130
    int nt = blockIdx.x, b = blockIdx.y, n0 = nt * TN;
    int tid = threadIdx.x, tx = tid & 31, ty = tid >> 5;

    for (int idx = tid; idx < 32 * 128; idx += 256) {
        int j = idx & 31, n = idx >> 5;
        Ej[j * 130 + n] = g_basis[(n0 + n) * JD + j];
    }
    float4 x4 = *(const float4*)&x[(size_t)b * NN + n0 + tx * 4];
    float4 t4 = *(const float4*)&t[(size_t)b * NN + n0 + tx * 4];
#pragma unroll
    for (int u = 0; u < 8; u++) {
        int c = ty + 8 * u;
        float w0 = __ldg(w + c), w1 = __ldg(w + WW + c), bb = __ldg(bias + c);
        float4 v;
        v.x = fmaf(x4.x, w0, fmaf(t4.x, w1, bb));
        v.y = fmaf(x4.y, w0, fmaf(t4.y, w1, bb));
        v.z = fmaf(x4.z, w0, fmaf(t4.z, w1, bb));
        v.w = fmaf(x4.w, w0, fmaf(t4.w, w1, bb));
        *(float4*)&g_h0[(size_t)(b * WW + c) * NN + n0 + tx * 4] = v;
        *(float4*)&Ts[c * 132 + tx * 4] = v;
    }
    __syncthreads();
    dft_phase(Ts, Ej, b, nt, tx, ty);
}

// ---------------- mode mixing: reduce partials + complex mix + scale -------
// grid 64 (b), 256 threads.
__global__ void __launch_bounds__(256) mode_mix_kernel(int l) {
    __shared__ float Fs[WW * JD];   // [i][j]
    int b = blockIdx.x, tid = threadIdx.x;
#pragma unroll
    for (int q = 0; q < 8; q++) {
        int idx = tid + 256 * q;
        const float* gp = g_part + (size_t)b * NT * WW * JD + idx;
        float a = 0.0f;
#pragma unroll 8
        for (int nt = 0; nt < NT; nt++) a += gp[nt * WW * JD];
        Fs[idx] = a;
    }
    __syncthreads();
#pragma unroll
    for (int q = 0; q < 4; q++) {
        int om = tid + 256 * q;
        int o = om & 63, m = om >> 6;
        float ar = 0.0f, ai = 0.0f;
        const float* wp = g_wt + (size_t)((l * MODES + m) * WW) * 128 + o;
#pragma unroll 4
        for (int i = 0; i < WW; i++) {
            float fr = Fs[i * JD + 2 * m], fi = Fs[i * JD + 2 * m + 1];
            float wr = wp[i * 128], wi = wp[i * 128 + 64];
            ar = fmaf(fr, wr, fmaf(-fi, wi, ar));
            ai = fmaf(fr, wi, fmaf(fi, wr, ai));
        }
        float sc = (m == 0) ? (1.0f / NN) : (2.0f / NN);
        g_mixed[(b * WW + o) * JD + 2 * m]     = ar * sc;
        g_mixed[(b * WW + o) * JD + 2 * m + 1] = ai * sc;
    }
}

// ---------------- fused layer: irfft + conv + bias (+GELU) (+DFT) ----------
// block (nt, b): C[64o x 128n] = A[64o x 96k] @ B[96k x 128n]
__global__ void __launch_bounds__(256) fused_layer_kernel(int src,
        const float* __restrict__ cw, const float* __restrict__ cb,
        int l, int do_gelu, int do_dft) {
    extern __shared__ float sm[];
    float* As = sm;                // 64*96 = 6144   (reused as Ej 32*130)
    float* Bs = sm + 64 * KF;      // 96*132 = 12672 (reused as Ts 64*132)
    const float* __restrict__ hin = src ? g_h1 : g_h0;
    float* __restrict__ hout      = src ? g_h0 : g_h1;
    int nt = blockIdx.x, b = blockIdx.y, n0 = nt * TN;
    int tid = threadIdx.x, tx = tid & 31, ty = tid >> 5;

    for (int idx = tid; idx < 64 * 64; idx += 256) {
        int o = idx >> 6, c = idx & 63;
        As[o * KF + c] = cw[(l * WW + o) * WW + c];
    }
    for (int idx = tid; idx < 64 * 32; idx += 256) {
        int o = idx >> 5, j = idx & 31;
        As[o * KF + 64 + j] = g_mixed[(b * WW + o) * JD + j];
    }
    for (int idx = tid; idx < 64 * 128; idx += 256) {
        int c = idx >> 7, n = idx & 127;
        Bs[c * 132 + n] = hin[(size_t)(b * WW + c) * NN + n0 + n];
    }
    for (int idx = tid; idx < 32 * 128; idx += 256) {
        int j = idx & 31, n = idx >> 5;
        Bs[(64 + j) * 132 + n] = g_basis[(n0 + n) * JD + j];
    }
    __syncthreads();

    ull acc[8][2];
#pragma unroll
    for (int u = 0; u < 8; u++) { acc[u][0] = 0ULL; acc[u][1] = 0ULL; }

#pragma unroll 4
    for (int k4 = 0; k4 < KF / 4; k4++) {
        float4 a4[8];
#pragma unroll
        for (int u = 0; u < 8; u++)
            a4[u] = *(const float4*)&As[(ty + 8 * u) * KF + k4 * 4];
#pragma unroll
        for (int kk = 0; kk < 4; kk++) {
            float4 bq = *(const float4*)&Bs[(k4 * 4 + kk) * 132 + tx * 4];
            ull b0 = pk2(bq.x, bq.y), b1 = pk2(bq.z, bq.w);
#pragma unroll
            for (int u = 0; u < 8; u++) {
                float a = (&a4[u].x)[kk];
                ull aa = pk2(a, a);
                acc[u][0] = fma2(aa, b0, acc[u][0]);
                acc[u][1] = fma2(aa, b1, acc[u][1]);
            }
        }
    }
    __syncthreads();   // done reading As/Bs; safe to repurpose

    float* Ts = Bs;    // [64][132]
    float* Ej = As;    // [32][130]
    if (do_dft) {
        for (int idx = tid; idx < 32 * 128; idx += 256) {
            int j = idx & 31, n = idx >> 5;
            Ej[j * 130 + n] = g_basis[(n0 + n) * JD + j];
        }
    }
#pragma unroll
    for (int u = 0; u < 8; u++) {
        int o = ty + 8 * u;
        float bias = __ldg(cb + l * WW + o);
        float4 v;
        upk2(acc[u][0], v.x, v.y);
        upk2(acc[u][1], v.z, v.w);
        v.x += bias; v.y += bias; v.z += bias; v.w += bias;
        if (do_gelu) {
            v.x = gelu_exact(v.x); v.y = gelu_exact(v.y);
            v.z = gelu_exact(v.z); v.w = gelu_exact(v.w);
        }
        *(float4*)&hout[(size_t)(b * WW + o) * NN + n0 + tx * 4] = v;
        if (do_dft) *(float4*)&Ts[o * 132 + tx * 4] = v;
    }
    if (do_dft) {
        __syncthreads();
        dft_phase(Ts, Ej, b, nt, tx, ty);
    }
}

// ---------------- head: fc1 + GELU + fc2 -----------------------------------
__global__ void __launch_bounds__(256) head_kernel(int src,
        const float* __restrict__ fc1w, const float* __restrict__ fc1b,
        const float* __restrict__ fc2w, const float* __restrict__ fc2b,
        float* __restrict__ out) {
    extern __shared__ float smh[];
    float* Hs  = smh;                  // 64*132
    float* W1s = smh + 64 * 132;       // 64*128 (j-permuted)
    float* Gs  = W1s + 64 * 128;       // 128*128
    __shared__ float ps[256];
    const float* __restrict__ h = src ? g_h1 : g_h0;
    int nt = blockIdx.x, b = blockIdx.y, n0 = nt * TN;
    int tid = threadIdx.x, tx = tid & 31, ty = tid >> 5;

    for (int idx = tid; idx < 64 * 128; idx += 256) {
        int c = idx >> 7, n = idx & 127;
        Hs[c * 132 + n] = h[(size_t)(b * WW + c) * NN + n0 + n];
    }
    // perm(j) = (j&7)*16 + (j>>3); thread ty slot u reads ty*16+u -> j = 8u+ty
    for (int idx = tid; idx < 64 * 128; idx += 256) {
        int k = idx >> 7, j = idx & 127;
        W1s[k * 128 + ((j & 7) * 16 + (j >> 3))] = fc1w[idx];
    }
    __syncthreads();

    ull acc[16][2];
#pragma unroll
    for (int u = 0; u < 16; u++) { acc[u][0] = 0ULL; acc[u][1] = 0ULL; }

#pragma unroll 4
    for (int k = 0; k < 64; k++) {
        float4 bq = *(const float4*)&Hs[k * 132 + tx * 4];
        ull b0 = pk2(bq.x, bq.y), b1 = pk2(bq.z, bq.w);
        float4 a4[4];
#pragma unroll
        for (int q = 0; q < 4; q++)
            a4[q] = *(const float4*)&W1s[k * 128 + ty * 16 + 4 * q];
#pragma unroll
        for (int u = 0; u < 16; u++) {
            float a = (&a4[u >> 2].x)[u & 3];
            ull aa = pk2(a, a);
            acc[u][0] = fma2(aa, b0, acc[u][0]);
            acc[u][1] = fma2(aa, b1, acc[u][1]);
        }
    }

#pragma unroll
    for (int u = 0; u < 16; u++) {
        int j = 8 * u + ty;
        float bj = __ldg(fc1b + j);
        float4 v;
        upk2(acc[u][0], v.x, v.y);
        upk2(acc[u][1], v.z, v.w);
        v.x = gelu_exact(v.x + bj); v.y = gelu_exact(v.y + bj);
        v.z = gelu_exact(v.z + bj); v.w = gelu_exact(v.w + bj);
        *(float4*)&Gs[j * 128 + tx * 4] = v;
    }
    __syncthreads();

    int n = tid & 127, half = tid >> 7;
    float s = 0.0f;
    int j0 = half * 64;
#pragma unroll 8
    for (int j = 0; j < 64; j++)
        s = fmaf(__ldg(fc2w + j0 + j), Gs[(j0 + j) * 128 + n], s);
    ps[tid] = s;
    __syncthreads();
    if (tid < 128)
        out[(size_t)b * NN + n0 + tid] = ps[tid] + ps[128 + tid] + __ldg(fc2b);
}

// ---------------- launch orchestration ------------------------------------
extern "C" void kernel_launch(void* const* d_in, const int* in_sizes, int n_in,
                              void* d_out, int out_size) {
    const float* x     = (const float*)d_in[0];
    const float* t     = (const float*)d_in[1];
    const float* fc0_w = (const float*)d_in[2];
    const float* fc0_b = (const float*)d_in[3];
    const float* sw_r  = (const float*)d_in[4];
    const float* sw_i  = (const float*)d_in[5];
    const float* cw    = (const float*)d_in[6];
    const float* cb    = (const float*)d_in[7];
    const float* fc1_w = (const float*)d_in[8];
    const float* fc1_b = (const float*)d_in[9];
    const float* fc2_w = (const float*)d_in[10];
    const float* fc2_b = (const float*)d_in[11];
    float* out = (float*)d_out;

    const int smem_fc0   = (64 * 132 + 32 * 130) * 4;            // 50432
    const int smem_fused = (64 * KF + KF * 132) * 4;             // 75264
    const int smem_head  = (64 * 132 + 64 * 128 + 128 * 128) * 4; // 132096

    cudaFuncSetAttribute(fc0_dft_kernel,
                         cudaFuncAttributeMaxDynamicSharedMemorySize, smem_fc0);
    cudaFuncSetAttribute(fused_layer_kernel,
                         cudaFuncAttributeMaxDynamicSharedMemorySize, smem_fused);
    cudaFuncSetAttribute(head_kernel,
                         cudaFuncAttributeMaxDynamicSharedMemorySize, smem_head);

    init_basis_kernel<<<512, 256>>>();
    transpose_w_kernel<<<1024, 256>>>(sw_r, sw_i);
    fc0_dft_kernel<<<dim3(NT, Bb), 256, smem_fc0>>>(x, t, fc0_w, fc0_b);

    int src = 0;  // current h buffer: 0 -> g_h0
    for (int l = 0; l < NL; l++) {
        mode_mix_kernel<<<Bb, 256>>>(l);
        fused_layer_kernel<<<dim3(NT, Bb), 256, smem_fused>>>(
            src, cw, cb, l, (l < NL - 1) ? 1 : 0, (l < NL - 1) ? 1 : 0);
        src ^= 1;
    }
    head_kernel<<<dim3(NT, Bb), 256, smem_head>>>(
        src, fc1_w, fc1_b, fc2_w, fc2_b, out);
}

// round 10
// speedup vs baseline: 1.2779x; 1.1852x over previous
#include <cuda_runtime.h>
#include <math.h>

#define Bb     64
#define NN     8192
#define WW     64
#define MODES  16
#define NL     4
#define JD     32          // 2*MODES real coefficients
#define KF     96          // 64 channels + 32 basis rows
#define NT     64          // n-tiles of 128
#define TN     128
#define RG     8           // reduction groups (NT/RG tiles each)

typedef unsigned long long ull;

// ---------------- device scratch (static, allocation-free) ----------------
__device__ float g_h0[(size_t)Bb * WW * NN];          // 128 MB
__device__ float g_h1[(size_t)Bb * WW * NN];          // 128 MB
__device__ float g_part[(size_t)Bb * NT * WW * JD];   // per-tile DFT partials (32 MB)
__device__ float g_red[(size_t)Bb * RG * WW * JD];    // stage-1 reduced partials (4 MB)
__device__ float g_mixed[Bb * WW * JD];               // scaled mixed modes
__device__ float g_basis[NN * JD];                    // [n][j]: cos / -sin
__device__ float g_wt[NL * MODES * WW * 2 * WW];      // [(l,m,i)][re(64)|im(64)]

// ---------------- packed f32x2 helpers ------------------------------------
__device__ __forceinline__ ull pk2(float lo, float hi) {
    ull r; asm("mov.b64 %0,{%1,%2};" : "=l"(r) : "f"(lo), "f"(hi)); return r;
}
__device__ __forceinline__ void upk2(ull v, float& lo, float& hi) {
    asm("mov.b64 {%0,%1},%2;" : "=f"(lo), "=f"(hi) : "l"(v));
}
__device__ __forceinline__ ull fma2(ull a, ull b, ull c) {
    ull d; asm("fma.rn.f32x2 %0,%1,%2,%3;" : "=l"(d) : "l"(a), "l"(b), "l"(c)); return d;
}

__device__ __forceinline__ float gelu_exact(float v) {
    return 0.5f * v * (1.0f + erff(v * 0.70710678118654752f));
}

// ---------------- basis table: [n][2m]=cos, [2m+1]=-sin --------------------
__global__ void init_basis_kernel() {
    int idx = blockIdx.x * blockDim.x + threadIdx.x;   // NN*MODES
    if (idx >= NN * MODES) return;
    int m = idx & (MODES - 1);
    int n = idx >> 4;
    int prod = (n * m) & (NN - 1);
    float ang = (float)prod * (6.2831853071795864769f / (float)NN);
    float s, c;
    sincosf(ang, &s, &c);
    g_basis[n * JD + 2 * m]     = c;
    g_basis[n * JD + 2 * m + 1] = -s;
}

// ---------------- transpose spectral weights to [(l,m,i)][re|im] -----------
__global__ void transpose_w_kernel(const float* __restrict__ swr,
                                   const float* __restrict__ swi) {
    int idx = blockIdx.x * blockDim.x + threadIdx.x;   // NL*MODES*W*W
    if (idx >= NL * MODES * WW * WW) return;
    int o = idx & 63;
    int i = (idx >> 6) & 63;
    int m = (idx >> 12) & 15;
    int l = idx >> 16;
    int src = (((l * WW + i) * WW + o) << 4) + m;
    int dst = (((l * MODES + m) * WW + i) << 7);
    g_wt[dst + o]      = swr[src];
    g_wt[dst + 64 + o] = swi[src];
}

// ---------------- shared DFT-partial phase ---------------------------------
__device__ __forceinline__ void dft_phase(const float* __restrict__ Ts,
                                          const float* __restrict__ Ej,
                                          int b, int nt, int tx, int ty) {
    ull acc[8];
#pragma unroll
    for (int u = 0; u < 8; u++) acc[u] = 0ULL;
#pragma unroll 8
    for (int n2 = 0; n2 < 64; n2++) {
        ull e2 = *(const ull*)&Ej[tx * 130 + 2 * n2];
#pragma unroll
        for (int u = 0; u < 8; u++) {
            ull t2 = *(const ull*)&Ts[(ty + 8 * u) * 132 + 2 * n2];
            acc[u] = fma2(t2, e2, acc[u]);
        }
    }
    float* gp = g_part + (size_t)(b * NT + nt) * WW * JD;
#pragma unroll
    for (int u = 0; u < 8; u++) {
        float lo, hi; upk2(acc[u], lo, hi);
        gp[(ty + 8 * u) * JD + tx] = lo + hi;
    }
}

// ---------------- fc0 tile + DFT partial -----------------------------------
__global__ void __launch_bounds__(256) fc0_dft_kernel(
        const float* __restrict__ x, const float* __restrict__ t,
        const float* __restrict__ w, const float* __restrict__ bias) {
    extern __shared__ float sm[];
    float* Ts = sm;                // 64*132
    float* Ej = sm + 64 * 132;     // 32*130
    int nt = blockIdx.x, b = blockIdx.y, n0 = nt * TN;
    int tid = threadIdx.x, tx = tid & 31, ty = tid >> 5;

    for (int idx = tid; idx < 32 * 128; idx += 256) {
        int j = idx & 31, n = idx >> 5;
        Ej[j * 130 + n] = g_basis[(n0 + n) * JD + j];
    }
    float4 x4 = *(const float4*)&x[(size_t)b * NN + n0 + tx * 4];
    float4 t4 = *(const float4*)&t[(size_t)b * NN + n0 + tx * 4];
#pragma unroll
    for (int u = 0; u < 8; u++) {
        int c = ty + 8 * u;
        float w0 = __ldg(w + c), w1 = __ldg(w + WW + c), bb = __ldg(bias + c);
        float4 v;
        v.x = fmaf(x4.x, w0, fmaf(t4.x, w1, bb));
        v.y = fmaf(x4.y, w0, fmaf(t4.y, w1, bb));
        v.z = fmaf(x4.z, w0, fmaf(t4.z, w1, bb));
        v.w = fmaf(x4.w, w0, fmaf(t4.w, w1, bb));
        *(float4*)&g_h0[(size_t)(b * WW + c) * NN + n0 + tx * 4] = v;
        *(float4*)&Ts[c * 132 + tx * 4] = v;
    }
    __syncthreads();
    dft_phase(Ts, Ej, b, nt, tx, ty);
}

// ---------------- stage-1 reduction: 64 tiles -> 8 groups ------------------
// grid (RG, Bb), 256 threads. Each block sums NT/RG=8 tiles of 2048 floats.
__global__ void __launch_bounds__(256) reduce_part_kernel() {
    int g = blockIdx.x, b = blockIdx.y, tid = threadIdx.x;
    const float* gp = g_part + (size_t)(b * NT + g * (NT / RG)) * WW * JD;
    float* gr = g_red + (size_t)(b * RG + g) * WW * JD;
#pragma unroll
    for (int q = 0; q < 8; q++) {
        int idx = tid + 256 * q;
        float a = 0.0f;
#pragma unroll
        for (int nt = 0; nt < NT / RG; nt++) a += gp[(size_t)nt * WW * JD + idx];
        gr[idx] = a;
    }
}

// ---------------- mode mixing: final reduce + complex mix + scale ----------
// grid 64 (b), 256 threads.
__global__ void __launch_bounds__(256) mode_mix_kernel(int l) {
    __shared__ float Fs[WW * JD];   // [i][j]
    int b = blockIdx.x, tid = threadIdx.x;
#pragma unroll
    for (int q = 0; q < 8; q++) {
        int idx = tid + 256 * q;
        const float* gr = g_red + (size_t)b * RG * WW * JD + idx;
        float a = 0.0f;
#pragma unroll
        for (int g = 0; g < RG; g++) a += gr[(size_t)g * WW * JD];
        Fs[idx] = a;
    }
    __syncthreads();
#pragma unroll
    for (int q = 0; q < 4; q++) {
        int om = tid + 256 * q;
        int o = om & 63, m = om >> 6;
        float ar = 0.0f, ai = 0.0f;
        const float* wp = g_wt + (size_t)((l * MODES + m) * WW) * 128 + o;
#pragma unroll 4
        for (int i = 0; i < WW; i++) {
            float fr = Fs[i * JD + 2 * m], fi = Fs[i * JD + 2 * m + 1];
            float wr = wp[i * 128], wi = wp[i * 128 + 64];
            ar = fmaf(fr, wr, fmaf(-fi, wi, ar));
            ai = fmaf(fr, wi, fmaf(fi, wr, ai));
        }
        float sc = (m == 0) ? (1.0f / NN) : (2.0f / NN);
        g_mixed[(b * WW + o) * JD + 2 * m]     = ar * sc;
        g_mixed[(b * WW + o) * JD + 2 * m + 1] = ai * sc;
    }
}

// ---------------- shared GEMM phase for the fused layers -------------------
// Loads As (cw|mixed) + Bs (h|basis), computes acc[8][2] = 8o x 4n per thread.
__device__ __forceinline__ void layer_gemm(float* As, float* Bs,
        const float* __restrict__ hin, const float* __restrict__ cw,
        int l, int b, int n0, int tid, int tx, int ty, ull acc[8][2]) {
    for (int idx = tid; idx < 64 * 64; idx += 256) {
        int o = idx >> 6, c = idx & 63;
        As[o * KF + c] = cw[(l * WW + o) * WW + c];
    }
    for (int idx = tid; idx < 64 * 32; idx += 256) {
        int o = idx >> 5, j = idx & 31;
        As[o * KF + 64 + j] = g_mixed[(b * WW + o) * JD + j];
    }
    for (int idx = tid; idx < 64 * 128; idx += 256) {
        int c = idx >> 7, n = idx & 127;
        Bs[c * 132 + n] = hin[(size_t)(b * WW + c) * NN + n0 + n];
    }
    for (int idx = tid; idx < 32 * 128; idx += 256) {
        int j = idx & 31, n = idx >> 5;
        Bs[(64 + j) * 132 + n] = g_basis[(n0 + n) * JD + j];
    }
    __syncthreads();

#pragma unroll
    for (int u = 0; u < 8; u++) { acc[u][0] = 0ULL; acc[u][1] = 0ULL; }

#pragma unroll 4
    for (int k4 = 0; k4 < KF / 4; k4++) {
        float4 a4[8];
#pragma unroll
        for (int u = 0; u < 8; u++)
            a4[u] = *(const float4*)&As[(ty + 8 * u) * KF + k4 * 4];
#pragma unroll
        for (int kk = 0; kk < 4; kk++) {
            float4 bq = *(const float4*)&Bs[(k4 * 4 + kk) * 132 + tx * 4];
            ull b0 = pk2(bq.x, bq.y), b1 = pk2(bq.z, bq.w);
#pragma unroll
            for (int u = 0; u < 8; u++) {
                float a = (&a4[u].x)[kk];
                ull aa = pk2(a, a);
                acc[u][0] = fma2(aa, b0, acc[u][0]);
                acc[u][1] = fma2(aa, b1, acc[u][1]);
            }
        }
    }
    __syncthreads();   // done reading As/Bs; safe to repurpose
}

// ---------------- fused layer 0..2: irfft + conv + bias + GELU + DFT -------
__global__ void __launch_bounds__(256) fused_layer_kernel(int src,
        const float* __restrict__ cw, const float* __restrict__ cb, int l) {
    extern __shared__ float sm[];
    float* As = sm;                // 64*96  (reused as Ej 32*130)
    float* Bs = sm + 64 * KF;      // 96*132 (reused as Ts 64*132)
    const float* __restrict__ hin = src ? g_h1 : g_h0;
    float* __restrict__ hout      = src ? g_h0 : g_h1;
    int nt = blockIdx.x, b = blockIdx.y, n0 = nt * TN;
    int tid = threadIdx.x, tx = tid & 31, ty = tid >> 5;

    ull acc[8][2];
    layer_gemm(As, Bs, hin, cw, l, b, n0, tid, tx, ty, acc);

    float* Ts = Bs;    // [64][132]
    float* Ej = As;    // [32][130]
    for (int idx = tid; idx < 32 * 128; idx += 256) {
        int j = idx & 31, n = idx >> 5;
        Ej[j * 130 + n] = g_basis[(n0 + n) * JD + j];
    }
#pragma unroll
    for (int u = 0; u < 8; u++) {
        int o = ty + 8 * u;
        float bias = __ldg(cb + l * WW + o);
        float4 v;
        upk2(acc[u][0], v.x, v.y);
        upk2(acc[u][1], v.z, v.w);
        v.x = gelu_exact(v.x + bias); v.y = gelu_exact(v.y + bias);
        v.z = gelu_exact(v.z + bias); v.w = gelu_exact(v.w + bias);
        *(float4*)&hout[(size_t)(b * WW + o) * NN + n0 + tx * 4] = v;
        *(float4*)&Ts[o * 132 + tx * 4] = v;
    }
    __syncthreads();
    dft_phase(Ts, Ej, b, nt, tx, ty);
}

// ---------------- fused LAST layer: conv tile + fc1 + GELU + fc2 -----------
// No h write, no DFT. Tile (no gelu) -> Ts; then fc1/gelu/fc2 in-block.
__global__ void __launch_bounds__(256) fused_last_kernel(int src,
        const float* __restrict__ cw, const float* __restrict__ cb,
        const float* __restrict__ fc1w, const float* __restrict__ fc1b,
        const float* __restrict__ fc2w, const float* __restrict__ fc2b,
        float* __restrict__ out) {
    extern __shared__ float sm[];
    float* As = sm;                // 64*96
    float* Bs = sm + 64 * KF;      // 96*132
    __shared__ float ps2[8 * 128];
    const float* __restrict__ hin = src ? g_h1 : g_h0;
    int nt = blockIdx.x, b = blockIdx.y, n0 = nt * TN;
    int tid = threadIdx.x, tx = tid & 31, ty = tid >> 5;

    ull acc[8][2];
    layer_gemm(As, Bs, hin, cw, NL - 1, b, n0, tid, tx, ty, acc);

    // repurpose: Ts [64][132] at sm[0..8448), W1s [64][128] at sm[8448..16640)
    float* Ts  = sm;
    float* W1s = sm + 64 * 132;
#pragma unroll
    for (int u = 0; u < 8; u++) {
        int o = ty + 8 * u;
        float bias = __ldg(cb + (NL - 1) * WW + o);
        float4 v;
        upk2(acc[u][0], v.x, v.y);
        upk2(acc[u][1], v.z, v.w);
        v.x += bias; v.y += bias; v.z += bias; v.w += bias;   // no gelu on last layer
        *(float4*)&Ts[o * 132 + tx * 4] = v;
    }
    // perm(j) = (j&7)*16 + (j>>3); thread ty slot u reads ty*16+u -> j = 8u+ty
    for (int idx = tid; idx < 64 * 128; idx += 256) {
        int k = idx >> 7, j = idx & 127;
        W1s[k * 128 + ((j & 7) * 16 + (j >> 3))] = fc1w[idx];
    }
    __syncthreads();

    ull acc2[16][2];
#pragma unroll
    for (int u = 0; u < 16; u++) { acc2[u][0] = 0ULL; acc2[u][1] = 0ULL; }

#pragma unroll 4
    for (int k = 0; k < 64; k++) {
        float4 bq = *(const float4*)&Ts[k * 132 + tx * 4];
        ull b0 = pk2(bq.x, bq.y), b1 = pk2(bq.z, bq.w);
        float4 a4[4];
#pragma unroll
        for (int q = 0; q < 4; q++)
            a4[q] = *(const float4*)&W1s[k * 128 + ty * 16 + 4 * q];
#pragma unroll
        for (int u = 0; u < 16; u++) {
            float a = (&a4[u >> 2].x)[u & 3];
            ull aa = pk2(a, a);
            acc2[u][0] = fma2(aa, b0, acc2[u][0]);
            acc2[u][1] = fma2(aa, b1, acc2[u][1]);
        }
    }

    float sacc[4] = {0.0f, 0.0f, 0.0f, 0.0f};
#pragma unroll
    for (int u = 0; u < 16; u++) {
        int j = 8 * u + ty;
        float bj = __ldg(fc1b + j);
        float w2 = __ldg(fc2w + j);
        float4 v;
        upk2(acc2[u][0], v.x, v.y);
        upk2(acc2[u][1], v.z, v.w);
        sacc[0] = fmaf(w2, gelu_exact(v.x + bj), sacc[0]);
        sacc[1] = fmaf(w2, gelu_exact(v.y + bj), sacc[1]);
        sacc[2] = fmaf(w2, gelu_exact(v.z + bj), sacc[2]);
        sacc[3] = fmaf(w2, gelu_exact(v.w + bj), sacc[3]);
    }
#pragma unroll
    for (int i = 0; i < 4; i++) ps2[ty * 128 + tx * 4 + i] = sacc[i];
    __syncthreads();

    if (tid < 128) {
        float s = __ldg(fc2b);
#pragma unroll
        for (int g = 0; g < 8; g++) s += ps2[g * 128 + tid];
        out[(size_t)b * NN + n0 + tid] = s;
    }
}

// ---------------- launch orchestration ------------------------------------
extern "C" void kernel_launch(void* const* d_in, const int* in_sizes, int n_in,
                              void* d_out, int out_size) {
    const float* x     = (const float*)d_in[0];
    const float* t     = (const float*)d_in[1];
    const float* fc0_w = (const float*)d_in[2];
    const float* fc0_b = (const float*)d_in[3];
    const float* sw_r  = (const float*)d_in[4];
    const float* sw_i  = (const float*)d_in[5];
    const float* cw    = (const float*)d_in[6];
    const float* cb    = (const float*)d_in[7];
    const float* fc1_w = (const float*)d_in[8];
    const float* fc1_b = (const float*)d_in[9];
    const float* fc2_w = (const float*)d_in[10];
    const float* fc2_b = (const float*)d_in[11];
    float* out = (float*)d_out;

    const int smem_fc0   = (64 * 132 + 32 * 130) * 4;   // 50432
    const int smem_fused = (64 * KF + KF * 132) * 4;    // 75264

    cudaFuncSetAttribute(fc0_dft_kernel,
                         cudaFuncAttributeMaxDynamicSharedMemorySize, smem_fc0);
    cudaFuncSetAttribute(fused_layer_kernel,
                         cudaFuncAttributeMaxDynamicSharedMemorySize, smem_fused);
    cudaFuncSetAttribute(fused_last_kernel,
                         cudaFuncAttributeMaxDynamicSharedMemorySize, smem_fused);

    init_basis_kernel<<<512, 256>>>();
    transpose_w_kernel<<<1024, 256>>>(sw_r, sw_i);
    fc0_dft_kernel<<<dim3(NT, Bb), 256, smem_fc0>>>(x, t, fc0_w, fc0_b);

    int src = 0;  // current h buffer: 0 -> g_h0
    for (int l = 0; l < NL - 1; l++) {
        reduce_part_kernel<<<dim3(RG, Bb), 256>>>();
        mode_mix_kernel<<<Bb, 256>>>(l);
        fused_layer_kernel<<<dim3(NT, Bb), 256, smem_fused>>>(src, cw, cb, l);
        src ^= 1;
    }
    reduce_part_kernel<<<dim3(RG, Bb), 256>>>();
    mode_mix_kernel<<<Bb, 256>>>(NL - 1);
    fused_last_kernel<<<dim3(NT, Bb), 256, smem_fused>>>(
        src, cw, cb, fc1_w, fc1_b, fc2_w, fc2_b, out);
}

// round 12
// speedup vs baseline: 1.4453x; 1.1310x over previous
#include <cuda_runtime.h>
#include <math.h>

#define Bb     64
#define NN     8192
#define WW     64
#define MODES  16
#define NL     4
#define JD     32          // 2*MODES real coefficients
#define KF     96          // 64 channels + 32 basis rows
#define NT     64          // n-tiles of 128
#define TN     128
#define RG     8           // reduction groups (NT/RG tiles each)
#define ATP    68          // At row pad (floats, 16B-aligned rows)

typedef unsigned long long ull;

// ---------------- device scratch (static, allocation-free) ----------------
__device__ float g_h0[(size_t)Bb * WW * NN];          // 128 MB
__device__ float g_h1[(size_t)Bb * WW * NN];          // 128 MB
__device__ float g_part[(size_t)Bb * NT * WW * JD];   // per-tile DFT partials (32 MB)
__device__ float g_red[(size_t)Bb * RG * WW * JD];    // stage-1 reduced partials (4 MB)
__device__ float g_mixed[Bb * WW * JD];               // scaled mixed modes
__device__ float g_basis[NN * JD];                    // [n][j]: cos / -sin
__device__ float g_wt[NL * MODES * WW * 2 * WW];      // [(l,m,i)][re(64)|im(64)]

// ---------------- packed f32x2 helpers ------------------------------------
__device__ __forceinline__ ull pk2(float lo, float hi) {
    ull r; asm("mov.b64 %0,{%1,%2};" : "=l"(r) : "f"(lo), "f"(hi)); return r;
}
__device__ __forceinline__ void upk2(ull v, float& lo, float& hi) {
    asm("mov.b64 {%0,%1},%2;" : "=f"(lo), "=f"(hi) : "l"(v));
}
__device__ __forceinline__ ull fma2(ull a, ull b, ull c) {
    ull d; asm("fma.rn.f32x2 %0,%1,%2,%3;" : "=l"(d) : "l"(a), "l"(b), "l"(c)); return d;
}

__device__ __forceinline__ float gelu_exact(float v) {
    return 0.5f * v * (1.0f + erff(v * 0.70710678118654752f));
}

// ---------------- basis table: [n][2m]=cos, [2m+1]=-sin --------------------
__global__ void init_basis_kernel() {
    int idx = blockIdx.x * blockDim.x + threadIdx.x;   // NN*MODES
    if (idx >= NN * MODES) return;
    int m = idx & (MODES - 1);
    int n = idx >> 4;
    int prod = (n * m) & (NN - 1);
    float ang = (float)prod * (6.2831853071795864769f / (float)NN);
    float s, c;
    sincosf(ang, &s, &c);
    g_basis[n * JD + 2 * m]     = c;
    g_basis[n * JD + 2 * m + 1] = -s;
}

// ---------------- transpose spectral weights to [(l,m,i)][re|im] -----------
__global__ void transpose_w_kernel(const float* __restrict__ swr,
                                   const float* __restrict__ swi) {
    int idx = blockIdx.x * blockDim.x + threadIdx.x;   // NL*MODES*W*W
    if (idx >= NL * MODES * WW * WW) return;
    int o = idx & 63;
    int i = (idx >> 6) & 63;
    int m = (idx >> 12) & 15;
    int l = idx >> 16;
    int src = (((l * WW + i) * WW + o) << 4) + m;
    int dst = (((l * MODES + m) * WW + i) << 7);
    g_wt[dst + o]      = swr[src];
    g_wt[dst + 64 + o] = swi[src];
}

// ---------------- shared DFT-partial phase ---------------------------------
__device__ __forceinline__ void dft_phase(const float* __restrict__ Ts,
                                          const float* __restrict__ Ej,
                                          int b, int nt, int tx, int ty) {
    ull acc[8];
#pragma unroll
    for (int u = 0; u < 8; u++) acc[u] = 0ULL;
#pragma unroll 8
    for (int n2 = 0; n2 < 64; n2++) {
        ull e2 = *(const ull*)&Ej[tx * 130 + 2 * n2];
#pragma unroll
        for (int u = 0; u < 8; u++) {
            ull t2 = *(const ull*)&Ts[(ty + 8 * u) * 132 + 2 * n2];
            acc[u] = fma2(t2, e2, acc[u]);
        }
    }
    float* gp = g_part + (size_t)(b * NT + nt) * WW * JD;
#pragma unroll
    for (int u = 0; u < 8; u++) {
        float lo, hi; upk2(acc[u], lo, hi);
        gp[(ty + 8 * u) * JD + tx] = lo + hi;
    }
}

// ---------------- fc0 tile + DFT partial -----------------------------------
__global__ void __launch_bounds__(256) fc0_dft_kernel(
        const float* __restrict__ x, const float* __restrict__ t,
        const float* __restrict__ w, const float* __restrict__ bias) {
    extern __shared__ float sm[];
    float* Ts = sm;                // 64*132
    float* Ej = sm + 64 * 132;     // 32*130
    int nt = blockIdx.x, b = blockIdx.y, n0 = nt * TN;
    int tid = threadIdx.x, tx = tid & 31, ty = tid >> 5;

    for (int idx = tid; idx < 32 * 128; idx += 256) {
        int j = idx & 31, n = idx >> 5;
        Ej[j * 130 + n] = g_basis[(n0 + n) * JD + j];
    }
    float4 x4 = *(const float4*)&x[(size_t)b * NN + n0 + tx * 4];
    float4 t4 = *(const float4*)&t[(size_t)b * NN + n0 + tx * 4];
#pragma unroll
    for (int u = 0; u < 8; u++) {
        int c = ty + 8 * u;
        float w0 = __ldg(w + c), w1 = __ldg(w + WW + c), bb = __ldg(bias + c);
        float4 v;
        v.x = fmaf(x4.x, w0, fmaf(t4.x, w1, bb));
        v.y = fmaf(x4.y, w0, fmaf(t4.y, w1, bb));
        v.z = fmaf(x4.z, w0, fmaf(t4.z, w1, bb));
        v.w = fmaf(x4.w, w0, fmaf(t4.w, w1, bb));
        *(float4*)&g_h0[(size_t)(b * WW + c) * NN + n0 + tx * 4] = v;
        *(float4*)&Ts[c * 132 + tx * 4] = v;
    }
    __syncthreads();
    dft_phase(Ts, Ej, b, nt, tx, ty);
}

// ---------------- stage-1 reduction: 64 tiles -> 8 groups ------------------
__global__ void __launch_bounds__(256) reduce_part_kernel() {
    int g = blockIdx.x, b = blockIdx.y, tid = threadIdx.x;
    const float* gp = g_part + (size_t)(b * NT + g * (NT / RG)) * WW * JD;
    float* gr = g_red + (size_t)(b * RG + g) * WW * JD;
#pragma unroll
    for (int q = 0; q < 8; q++) {
        int idx = tid + 256 * q;
        float a = 0.0f;
#pragma unroll
        for (int nt = 0; nt < NT / RG; nt++) a += gp[(size_t)nt * WW * JD + idx];
        gr[idx] = a;
    }
}

// ---------------- mode mixing: final reduce + complex mix + scale ----------
__global__ void __launch_bounds__(256) mode_mix_kernel(int l) {
    __shared__ float Fs[WW * JD];   // [i][j]
    int b = blockIdx.x, tid = threadIdx.x;
#pragma unroll
    for (int q = 0; q < 8; q++) {
        int idx = tid + 256 * q;
        const float* gr = g_red + (size_t)b * RG * WW * JD + idx;
        float a = 0.0f;
#pragma unroll
        for (int g = 0; g < RG; g++) a += gr[(size_t)g * WW * JD];
        Fs[idx] = a;
    }
    __syncthreads();
#pragma unroll
    for (int q = 0; q < 4; q++) {
        int om = tid + 256 * q;
        int o = om & 63, m = om >> 6;
        float ar = 0.0f, ai = 0.0f;
        const float* wp = g_wt + (size_t)((l * MODES + m) * WW) * 128 + o;
#pragma unroll 4
        for (int i = 0; i < WW; i++) {
            float fr = Fs[i * JD + 2 * m], fi = Fs[i * JD + 2 * m + 1];
            float wr = wp[i * 128], wi = wp[i * 128 + 64];
            ar = fmaf(fr, wr, fmaf(-fi, wi, ar));
            ai = fmaf(fr, wi, fmaf(fi, wr, ai));
        }
        float sc = (m == 0) ? (1.0f / NN) : (2.0f / NN);
        g_mixed[(b * WW + o) * JD + 2 * m]     = ar * sc;
        g_mixed[(b * WW + o) * JD + 2 * m + 1] = ai * sc;
    }
}

// ---------------- shared GEMM phase (o-pair packed operands) ---------------
// At[k][o] transposed A; Bs[k][n] h|basis. Thread: o = ty*8..+7 (4 pairs),
// n = tx*4..+3. acc[p][n] packs outputs (o=ty*8+2p, o+1).
__device__ __forceinline__ void layer_gemm(float* At, float* Bs,
        const float* __restrict__ hin, const float* __restrict__ cw,
        int l, int b, int n0, int tid, int tx, int ty, ull acc[4][4]) {
    for (int idx = tid; idx < 64 * 64; idx += 256) {
        int o = idx >> 6, c = idx & 63;
        At[c * ATP + o] = cw[(l * WW + o) * WW + c];
    }
    for (int idx = tid; idx < 64 * 32; idx += 256) {
        int o = idx >> 5, j = idx & 31;
        At[(64 + j) * ATP + o] = g_mixed[(b * WW + o) * JD + j];
    }
    for (int idx = tid; idx < 64 * 128; idx += 256) {
        int c = idx >> 7, n = idx & 127;
        Bs[c * 132 + n] = hin[(size_t)(b * WW + c) * NN + n0 + n];
    }
    for (int idx = tid; idx < 32 * 128; idx += 256) {
        int j = idx & 31, n = idx >> 5;
        Bs[(64 + j) * 132 + n] = g_basis[(n0 + n) * JD + j];
    }
    __syncthreads();

#pragma unroll
    for (int p = 0; p < 4; p++)
#pragma unroll
        for (int n = 0; n < 4; n++) acc[p][n] = 0ULL;

#pragma unroll 4
    for (int k = 0; k < KF; k++) {
        float4 aL = *(const float4*)&At[k * ATP + ty * 8];
        float4 aH = *(const float4*)&At[k * ATP + ty * 8 + 4];
        float4 bq = *(const float4*)&Bs[k * 132 + tx * 4];
        ull ap[4];
        ap[0] = pk2(aL.x, aL.y); ap[1] = pk2(aL.z, aL.w);
        ap[2] = pk2(aH.x, aH.y); ap[3] = pk2(aH.z, aH.w);
        ull bb[4];
        bb[0] = pk2(bq.x, bq.x); bb[1] = pk2(bq.y, bq.y);
        bb[2] = pk2(bq.z, bq.z); bb[3] = pk2(bq.w, bq.w);
#pragma unroll
        for (int p = 0; p < 4; p++)
#pragma unroll
            for (int n = 0; n < 4; n++)
                acc[p][n] = fma2(ap[p], bb[n], acc[p][n]);
    }
    __syncthreads();   // done reading At/Bs; safe to repurpose
}

// ---------------- fused layer 0..2: irfft + conv + bias + GELU + DFT -------
__global__ void __launch_bounds__(256) fused_layer_kernel(int src,
        const float* __restrict__ cw, const float* __restrict__ cb, int l) {
    extern __shared__ float sm[];
    float* At = sm;                 // [96][ATP]  (reused as Ej 32*130)
    float* Bs = sm + KF * ATP;      // [96][132]  (rows 0..63 reused as Ts)
    const float* __restrict__ hin = src ? g_h1 : g_h0;
    float* __restrict__ hout      = src ? g_h0 : g_h1;
    int nt = blockIdx.x, b = blockIdx.y, n0 = nt * TN;
    int tid = threadIdx.x, tx = tid & 31, ty = tid >> 5;

    ull acc[4][4];
    layer_gemm(At, Bs, hin, cw, l, b, n0, tid, tx, ty, acc);

    float* Ts = Bs;    // [64][132]
    float* Ej = At;    // [32][130]
    for (int idx = tid; idx < 32 * 128; idx += 256) {
        int j = idx & 31, n = idx >> 5;
        Ej[j * 130 + n] = g_basis[(n0 + n) * JD + j];
    }
#pragma unroll
    for (int p = 0; p < 4; p++) {
        int o0 = ty * 8 + 2 * p, o1 = o0 + 1;
        float bi0 = __ldg(cb + l * WW + o0);
        float bi1 = __ldg(cb + l * WW + o1);
        float4 v0, v1;
        upk2(acc[p][0], v0.x, v1.x);
        upk2(acc[p][1], v0.y, v1.y);
        upk2(acc[p][2], v0.z, v1.z);
        upk2(acc[p][3], v0.w, v1.w);
        v0.x = gelu_exact(v0.x + bi0); v0.y = gelu_exact(v0.y + bi0);
        v0.z = gelu_exact(v0.z + bi0); v0.w = gelu_exact(v0.w + bi0);
        v1.x = gelu_exact(v1.x + bi1); v1.y = gelu_exact(v1.y + bi1);
        v1.z = gelu_exact(v1.z + bi1); v1.w = gelu_exact(v1.w + bi1);
        *(float4*)&hout[(size_t)(b * WW + o0) * NN + n0 + tx * 4] = v0;
        *(float4*)&hout[(size_t)(b * WW + o1) * NN + n0 + tx * 4] = v1;
        *(float4*)&Ts[o0 * 132 + tx * 4] = v0;
        *(float4*)&Ts[o1 * 132 + tx * 4] = v1;
    }
    __syncthreads();
    dft_phase(Ts, Ej, b, nt, tx, ty);
}

// ---------------- fused LAST layer: conv tile + fc1 + GELU + fc2 -----------
__global__ void __launch_bounds__(256) fused_last_kernel(int src,
        const float* __restrict__ cw, const float* __restrict__ cb,
        const float* __restrict__ fc1w, const float* __restrict__ fc1b,
        const float* __restrict__ fc2w, const float* __restrict__ fc2b,
        float* __restrict__ out) {
    extern __shared__ float sm[];
    float* At  = sm;                        // [96][ATP]
    float* Bs  = sm + KF * ATP;             // [96][132]
    float* W1s = sm + KF * ATP + KF * 132;  // [64][132]
    __shared__ float ps2[8 * 128];
    const float* __restrict__ hin = src ? g_h1 : g_h0;
    int nt = blockIdx.x, b = blockIdx.y, n0 = nt * TN;
    int tid = threadIdx.x, tx = tid & 31, ty = tid >> 5;

    // W1s[k][j] straight layout (j-pairs naturally contiguous)
    for (int idx = tid; idx < 64 * 128; idx += 256) {
        int k = idx >> 7, j = idx & 127;
        W1s[k * 132 + j] = fc1w[idx];
    }

    ull acc[4][4];
    layer_gemm(At, Bs, hin, cw, NL - 1, b, n0, tid, tx, ty, acc);

    float* Ts = Bs;    // [64][132]
#pragma unroll
    for (int p = 0; p < 4; p++) {
        int o0 = ty * 8 + 2 * p, o1 = o0 + 1;
        float bi0 = __ldg(cb + (NL - 1) * WW + o0);
        float bi1 = __ldg(cb + (NL - 1) * WW + o1);
        float4 v0, v1;
        upk2(acc[p][0], v0.x, v1.x);
        upk2(acc[p][1], v0.y, v1.y);
        upk2(acc[p][2], v0.z, v1.z);
        upk2(acc[p][3], v0.w, v1.w);
        v0.x += bi0; v0.y += bi0; v0.z += bi0; v0.w += bi0;   // no gelu last layer
        v1.x += bi1; v1.y += bi1; v1.z += bi1; v1.w += bi1;
        *(float4*)&Ts[o0 * 132 + tx * 4] = v0;
        *(float4*)&Ts[o1 * 132 + tx * 4] = v1;
    }
    __syncthreads();

    // fc1 GEMM: thread j = ty*16..+15 (8 pairs), n = tx*4..+3
    ull acc2[8][4];
#pragma unroll
    for (int p = 0; p < 8; p++)
#pragma unroll
        for (int n = 0; n < 4; n++) acc2[p][n] = 0ULL;

#pragma unroll 4
    for (int k = 0; k < 64; k++) {
        float4 bq = *(const float4*)&Ts[k * 132 + tx * 4];
        ull bb[4];
        bb[0] = pk2(bq.x, bq.x); bb[1] = pk2(bq.y, bq.y);
        bb[2] = pk2(bq.z, bq.z); bb[3] = pk2(bq.w, bq.w);
        float4 w0 = *(const float4*)&W1s[k * 132 + ty * 16];
        float4 w1 = *(const float4*)&W1s[k * 132 + ty * 16 + 4];
        float4 w2 = *(const float4*)&W1s[k * 132 + ty * 16 + 8];
        float4 w3 = *(const float4*)&W1s[k * 132 + ty * 16 + 12];
        ull wp[8];
        wp[0] = pk2(w0.x, w0.y); wp[1] = pk2(w0.z, w0.w);
        wp[2] = pk2(w1.x, w1.y); wp[3] = pk2(w1.z, w1.w);
        wp[4] = pk2(w2.x, w2.y); wp[5] = pk2(w2.z, w2.w);
        wp[6] = pk2(w3.x, w3.y); wp[7] = pk2(w3.z, w3.w);
#pragma unroll
        for (int p = 0; p < 8; p++)
#pragma unroll
            for (int n = 0; n < 4; n++)
                acc2[p][n] = fma2(wp[p], bb[n], acc2[p][n]);
    }

    float sacc[4] = {0.0f, 0.0f, 0.0f, 0.0f};
#pragma unroll
    for (int p = 0; p < 8; p++) {
        int j0 = ty * 16 + 2 * p, j1 = j0 + 1;
        float bj0 = __ldg(fc1b + j0), bj1 = __ldg(fc1b + j1);
        float wz0 = __ldg(fc2w + j0), wz1 = __ldg(fc2w + j1);
#pragma unroll
        for (int n = 0; n < 4; n++) {
            float g0, g1;
            upk2(acc2[p][n], g0, g1);
            sacc[n] = fmaf(wz0, gelu_exact(g0 + bj0), sacc[n]);
            sacc[n] = fmaf(wz1, gelu_exact(g1 + bj1), sacc[n]);
        }
    }
#pragma unroll
    for (int i = 0; i < 4; i++) ps2[ty * 128 + tx * 4 + i] = sacc[i];
    __syncthreads();

    if (tid < 128) {
        float s = __ldg(fc2b);
#pragma unroll
        for (int g = 0; g < 8; g++) s += ps2[g * 128 + tid];
        out[(size_t)b * NN + n0 + tid] = s;
    }
}

// ---------------- launch orchestration ------------------------------------
extern "C" void kernel_launch(void* const* d_in, const int* in_sizes, int n_in,
                              void* d_out, int out_size) {
    const float* x     = (const float*)d_in[0];
    const float* t     = (const float*)d_in[1];
    const float* fc0_w = (const float*)d_in[2];
    const float* fc0_b = (const float*)d_in[3];
    const float* sw_r  = (const float*)d_in[4];
    const float* sw_i  = (const float*)d_in[5];
    const float* cw    = (const float*)d_in[6];
    const float* cb    = (const float*)d_in[7];
    const float* fc1_w = (const float*)d_in[8];
    const float* fc1_b = (const float*)d_in[9];
    const float* fc2_w = (const float*)d_in[10];
    const float* fc2_b = (const float*)d_in[11];
    float* out = (float*)d_out;

    const int smem_fc0   = (64 * 132 + 32 * 130) * 4;              // 50432
    const int smem_fused = (KF * ATP + KF * 132) * 4;              // 76800
    const int smem_last  = (KF * ATP + KF * 132 + 64 * 132) * 4;   // 110592

    cudaFuncSetAttribute(fc0_dft_kernel,
                         cudaFuncAttributeMaxDynamicSharedMemorySize, smem_fc0);
    cudaFuncSetAttribute(fused_layer_kernel,
                         cudaFuncAttributeMaxDynamicSharedMemorySize, smem_fused);
    cudaFuncSetAttribute(fused_last_kernel,
                         cudaFuncAttributeMaxDynamicSharedMemorySize, smem_last);

    init_basis_kernel<<<512, 256>>>();
    transpose_w_kernel<<<1024, 256>>>(sw_r, sw_i);
    fc0_dft_kernel<<<dim3(NT, Bb), 256, smem_fc0>>>(x, t, fc0_w, fc0_b);

    int src = 0;  // current h buffer: 0 -> g_h0
    for (int l = 0; l < NL - 1; l++) {
        reduce_part_kernel<<<dim3(RG, Bb), 256>>>();
        mode_mix_kernel<<<Bb, 256>>>(l);
        fused_layer_kernel<<<dim3(NT, Bb), 256, smem_fused>>>(src, cw, cb, l);
        src ^= 1;
    }
    reduce_part_kernel<<<dim3(RG, Bb), 256>>>();
    mode_mix_kernel<<<Bb, 256>>>(NL - 1);
    fused_last_kernel<<<dim3(NT, Bb), 256, smem_last>>>(
        src, cw, cb, fc1_w, fc1_b, fc2_w, fc2_b, out);
}